// round 12
// baseline (speedup 1.0000x reference)
#include <cuda_runtime.h>
#include <cuda_fp16.h>
#include <cstdint>

#define NB 32
#define NS 2048
#define ENC2 1024
#define DEC 1024
#define ATT 1024

#define BM 128
#define BN 128
#define BK 64                       // K halfs per chunk
#define ASTRH 72                    // smem row stride in halfs (144B): ldmatrix conflict-free
#define STG 3                       // cp.async pipeline stages
#define STAGE_H (BM * ASTRH)        // halfs per stage per array (9216)
#define STAGE_B (STAGE_H * 2)       // 18432 bytes
#define SMEM_DYN (STG * STAGE_B * 2)  // 110592 bytes

// scratch (no allocations allowed)
__device__ float  g_dp[NB * ATT];                       // decoder_proj + b_dec + b_enc
__device__ float  g_energy[NB * NS];                    // energies (b_e dropped)
__device__ __half g_ench[(size_t)NB * NS * ENC2];       // enc in fp16 (128 MB)
__device__ __half g_Wth[ATT * ENC2];                    // W_enc^T in fp16: Wt[n][k]

__device__ __forceinline__ uint32_t smem_u32(const void* p) {
    uint32_t a;
    asm("{ .reg .u64 t; cvta.to.shared.u64 t, %1; cvt.u32.u64 %0, t; }"
        : "=r"(a) : "l"(p));
    return a;
}
__device__ __forceinline__ uint2 f4_to_h4(float4 v) {
    half2 lo = __float22half2_rn(make_float2(v.x, v.y));
    half2 hi = __float22half2_rn(make_float2(v.z, v.w));
    uint2 u;
    u.x = *(uint32_t*)&lo;
    u.y = *(uint32_t*)&hi;
    return u;
}

// ---------------------------------------------------------------------------
// Kernel 0a: enc fp32 -> fp16; also zeroes g_dp and g_energy for this replay.
// ---------------------------------------------------------------------------
__global__ void k_convert(const float* __restrict__ enc) {
    const size_t total4 = (size_t)NB * NS * ENC2 / 4;   // 16M float4
    uint2* dst = (uint2*)g_ench;
    const float4* src = (const float4*)enc;
    const size_t gid = (size_t)blockIdx.x * blockDim.x + threadIdx.x;
    const size_t stride = (size_t)gridDim.x * blockDim.x;
    for (size_t p = gid; p < total4; p += stride)
        dst[p] = f4_to_h4(src[p]);
    for (size_t i = gid; i < NB * ATT; i += stride) g_dp[i] = 0.f;
    for (size_t i = gid; i < NB * NS; i += stride) g_energy[i] = 0.f;
}

// ---------------------------------------------------------------------------
// Kernel 0b: transpose W_enc into g_Wth (n-major, k contiguous, fp16)
// ---------------------------------------------------------------------------
__global__ void k_transpose(const float* __restrict__ W) {
    __shared__ float t[32][33];
    const int x = blockIdx.x * 32 + threadIdx.x;   // n
    const int y0 = blockIdx.y * 32;                // k base
    for (int j = threadIdx.y; j < 32; j += 8)
        t[j][threadIdx.x] = W[(y0 + j) * ATT + x];
    __syncthreads();
    const int k = blockIdx.y * 32 + threadIdx.x;
    const int n0 = blockIdx.x * 32;
    for (int j = threadIdx.y; j < 32; j += 8)
        g_Wth[(size_t)(n0 + j) * ENC2 + k] = __float2half(t[threadIdx.x][j]);
}

// ---------------------------------------------------------------------------
// Kernel 1: dec_proj + bias fold, d-split x4 (atomicAdd into zeroed g_dp).
// grid (8 a-chunks, 4 b-chunks, 4 d-chunks), 128 threads.
// ---------------------------------------------------------------------------
__global__ void k_decproj(const float* __restrict__ dh,
                          const float* __restrict__ Wd,
                          const float* __restrict__ bd,
                          const float* __restrict__ ben) {
    __shared__ float sdh[8][256];
    const int a  = blockIdx.x * 128 + threadIdx.x;
    const int b0 = blockIdx.y * 8;
    const int d0 = blockIdx.z * 256;

    for (int i = threadIdx.x; i < 8 * 256; i += 128)
        sdh[i >> 8][i & 255] = dh[(b0 + (i >> 8)) * DEC + d0 + (i & 255)];
    __syncthreads();

    float acc[8];
#pragma unroll
    for (int bb = 0; bb < 8; bb++) acc[bb] = 0.f;
#pragma unroll 4
    for (int d = 0; d < 256; d++) {
        const float w = Wd[(d0 + d) * ATT + a];
#pragma unroll
        for (int bb = 0; bb < 8; bb++) acc[bb] += w * sdh[bb][d];
    }
    const float bias = (blockIdx.z == 0) ? (bd[a] + ben[a]) : 0.f;
#pragma unroll
    for (int bb = 0; bb < 8; bb++)
        atomicAdd(&g_dp[(b0 + bb) * ATT + a], acc[bb] + bias);
}

// ---------------------------------------------------------------------------
// Kernel 2: fused energy GEMM, fp16 mma.sync + ldmatrix + 3-stage cp.async.
// CTA 128x128, K-chunk 64, 512 threads / 16 warps (4x4 grid, 32x32 warp
// tile), 2 CTAs/SM -> 8 warps/SMSP for latency hiding. tn fastest.
// ---------------------------------------------------------------------------
__global__ __launch_bounds__(512, 2)
void k_energy(const float* __restrict__ we_v) {
    extern __shared__ __align__(16) __half sh[];
    __half* As = sh;                     // [STG][STAGE_H]
    __half* Bs = sh + STG * STAGE_H;     // [STG][STAGE_H]

    const int tn = blockIdx.x;                  // 0..7   N tile (fastest)
    const int tm = blockIdx.y;                  // 0..511 M tile
    const int tid  = threadIdx.x;
    const int lane = tid & 31;
    const int warp = tid >> 5;                  // 0..15
    const int wm = warp >> 2;                   // 0..3
    const int wn = warp & 3;                    // 0..3

    float acc[2][4][4];
#pragma unroll
    for (int i = 0; i < 2; i++)
#pragma unroll
        for (int j = 0; j < 4; j++)
#pragma unroll
            for (int k = 0; k < 4; k++) acc[i][j][k] = 0.f;

    const __half* Ag = g_ench + (size_t)tm * BM * ENC2;
    const __half* Bg = g_Wth + (size_t)tn * BN * ENC2;
    const uint32_t asBase = smem_u32(As);
    const uint32_t bsBase = smem_u32(Bs);

    // loader: per chunk 1024 x 16B per array over 512 threads (2 each)
    auto load_chunk = [&](int kc) {
        const int st = kc - (kc / STG) * STG;           // kc % 3
        const __half* a = Ag + kc * BK;
        const __half* b = Bg + kc * BK;
        const uint32_t sA = asBase + st * STAGE_B;
        const uint32_t sB = bsBase + st * STAGE_B;
#pragma unroll
        for (int j = 0; j < 2; j++) {
            const int idx = tid + j * 512;              // 0..1023
            const int row = idx >> 3, c16 = idx & 7;
            const size_t so = (size_t)row * ENC2 + c16 * 8;
            const uint32_t dof = (uint32_t)(row * ASTRH + c16 * 8) * 2;
            asm volatile("cp.async.cg.shared.global [%0], [%1], 16;"
                         :: "r"(sA + dof), "l"(a + so));
            asm volatile("cp.async.cg.shared.global [%0], [%1], 16;"
                         :: "r"(sB + dof), "l"(b + so));
        }
        asm volatile("cp.async.commit_group;" ::: "memory");
    };

    // ldmatrix per-lane base addresses (stage 0)
    const uint32_t aBase = asBase
        + (uint32_t)((wm * 32 + (lane & 15)) * (ASTRH * 2))
        + (uint32_t)(((lane >> 4) & 1) * 16);
    const uint32_t bBase = bsBase
        + (uint32_t)((wn * 32 + ((lane >> 4) & 1) * 8 + (lane & 7)) * (ASTRH * 2))
        + (uint32_t)(((lane >> 3) & 1) * 16);

    load_chunk(0);
    load_chunk(1);

    const int NKT = ENC2 / BK;  // 16
    for (int kt = 0; kt < NKT; kt++) {
        if (kt < NKT - 1)
            asm volatile("cp.async.wait_group 1;" ::: "memory");
        else
            asm volatile("cp.async.wait_group 0;" ::: "memory");
        __syncthreads();   // chunk kt visible; stage (kt+2)%3 readers (iter kt-1) done

        if (kt + 2 < NKT) load_chunk(kt + 2);

        const int st = kt - (kt / STG) * STG;
        const uint32_t stOff = (uint32_t)(st * STAGE_B);
        const uint32_t aAddr = aBase + stOff;
        const uint32_t bAddr = bBase + stOff;

#pragma unroll
        for (int ks = 0; ks < 4; ks++) {       // four k16 steps per 64-chunk
            uint32_t af[2][4];
#pragma unroll
            for (int mt = 0; mt < 2; mt++) {
                asm volatile(
                    "ldmatrix.sync.aligned.m8n8.x4.shared.b16 {%0,%1,%2,%3}, [%4];"
                    : "=r"(af[mt][0]), "=r"(af[mt][1]), "=r"(af[mt][2]), "=r"(af[mt][3])
                    : "r"(aAddr + (uint32_t)(mt * 16 * ASTRH * 2 + ks * 32)));
            }
            uint32_t bf[4][2];
#pragma unroll
            for (int p = 0; p < 2; p++) {
                asm volatile(
                    "ldmatrix.sync.aligned.m8n8.x4.shared.b16 {%0,%1,%2,%3}, [%4];"
                    : "=r"(bf[2 * p][0]), "=r"(bf[2 * p][1]),
                      "=r"(bf[2 * p + 1][0]), "=r"(bf[2 * p + 1][1])
                    : "r"(bAddr + (uint32_t)(p * 16 * ASTRH * 2 + ks * 32)));
            }
#pragma unroll
            for (int mt = 0; mt < 2; mt++)
#pragma unroll
                for (int nt = 0; nt < 4; nt++) {
                    float* d = acc[mt][nt];
                    asm volatile(
                        "mma.sync.aligned.m16n8k16.row.col.f32.f16.f16.f32 "
                        "{%0,%1,%2,%3}, {%4,%5,%6,%7}, {%8,%9}, {%0,%1,%2,%3};"
                        : "+f"(d[0]), "+f"(d[1]), "+f"(d[2]), "+f"(d[3])
                        : "r"(af[mt][0]), "r"(af[mt][1]), "r"(af[mt][2]), "r"(af[mt][3]),
                          "r"(bf[nt][0]), "r"(bf[nt][1]));
                }
        }
    }

    // ---- epilogue: tanh, weight by w_e, row-reduce, atomic into g_energy ----
    const int b = tm >> 4;   // 16 M-tiles per batch
    __syncthreads();
    float* dp_s = (float*)As;
    float* we_s = dp_s + BN;
    if (tid < BN) {
        dp_s[tid] = g_dp[b * ATT + tn * BN + tid];
        we_s[tid] = we_v[tn * BN + tid];
    }
    __syncthreads();

    const int r = lane >> 2, c = lane & 3;
    const float* dpp = dp_s + wn * 32;
    const float* wep = we_s + wn * 32;

#pragma unroll
    for (int mt = 0; mt < 2; mt++) {
#pragma unroll
        for (int rr = 0; rr < 2; rr++) {
            float rsum = 0.f;
#pragma unroll
            for (int nt = 0; nt < 4; nt++) {
#pragma unroll
                for (int cc = 0; cc < 2; cc++) {
                    const int col = nt * 8 + c * 2 + cc;
                    const float x = acc[mt][nt][rr * 2 + cc] + dpp[col];
                    rsum += tanhf(x) * wep[col];
                }
            }
            rsum += __shfl_xor_sync(0xffffffffu, rsum, 1);
            rsum += __shfl_xor_sync(0xffffffffu, rsum, 2);
            if (c == 0) {
                const int row = tm * BM + wm * 32 + mt * 16 + rr * 8 + r;
                atomicAdd(&g_energy[row], rsum);
            }
        }
    }
}

// ---------------------------------------------------------------------------
// Kernel 3a: masked softmax (mask = int32). Also zeroes out_ctx for 3b atomics.
// ---------------------------------------------------------------------------
__global__ void k_softmax(const int* __restrict__ mask,
                          float* __restrict__ out_w,
                          float* __restrict__ out_ctx) {
    const int b = blockIdx.x, t = threadIdx.x;
    __shared__ float red[32];
    const float NEG = __int_as_float(0xff800000);

    out_ctx[b * ENC2 + t] = 0.f;

    float e0 = g_energy[b * NS + t];
    float e1 = g_energy[b * NS + 1024 + t];
    bool m0 = mask[b * NS + t] != 0;
    bool m1 = mask[b * NS + 1024 + t] != 0;

    float v = fmaxf(m0 ? e0 : NEG, m1 ? e1 : NEG);
#pragma unroll
    for (int o = 16; o; o >>= 1) v = fmaxf(v, __shfl_xor_sync(0xffffffffu, v, o));
    if ((t & 31) == 0) red[t >> 5] = v;
    __syncthreads();
    if (t < 32) {
        float x = red[t];
#pragma unroll
        for (int o = 16; o; o >>= 1) x = fmaxf(x, __shfl_xor_sync(0xffffffffu, x, o));
        red[t] = x;
    }
    __syncthreads();
    const float mx = red[0];
    __syncthreads();

    float x0 = m0 ? __expf(e0 - mx) : 0.f;
    float x1 = m1 ? __expf(e1 - mx) : 0.f;
    float s = x0 + x1;
#pragma unroll
    for (int o = 16; o; o >>= 1) s += __shfl_xor_sync(0xffffffffu, s, o);
    if ((t & 31) == 0) red[t >> 5] = s;
    __syncthreads();
    if (t < 32) {
        float x = red[t];
#pragma unroll
        for (int o = 16; o; o >>= 1) x += __shfl_xor_sync(0xffffffffu, x, o);
        red[t] = x;
    }
    __syncthreads();
    const float inv = 1.0f / red[0];

    out_w[b * NS + t]        = x0 * inv;
    out_w[b * NS + 1024 + t] = x1 * inv;
}

// ---------------------------------------------------------------------------
// Kernel 3b: context from fp16 enc, full-row vectorized, split-S x16.
// grid (32 b, 16 s-chunks), 256 threads, each owns 4 consecutive e (uint2/8B).
// ---------------------------------------------------------------------------
__global__ void k_context(const float* __restrict__ w,
                          float* __restrict__ out_ctx) {
    const int b = blockIdx.x;
    const int s0 = blockIdx.y * 128;
    const int e0 = threadIdx.x * 4;

    const float* wp = w + b * NS;
    const __half* ep = g_ench + (size_t)b * NS * ENC2 + e0;

    float a0 = 0.f, a1 = 0.f, a2 = 0.f, a3 = 0.f;
#pragma unroll 1
    for (int s = s0; s < s0 + 128; s += 4) {
#pragma unroll
        for (int j = 0; j < 4; j++) {
            const float ws = wp[s + j];
            const uint2 u = *(const uint2*)(ep + (size_t)(s + j) * ENC2);
            const float2 f01 = __half22float2(*(const half2*)&u.x);
            const float2 f23 = __half22float2(*(const half2*)&u.y);
            a0 += ws * f01.x;
            a1 += ws * f01.y;
            a2 += ws * f23.x;
            a3 += ws * f23.y;
        }
    }
    atomicAdd(&out_ctx[b * ENC2 + e0],     a0);
    atomicAdd(&out_ctx[b * ENC2 + e0 + 1], a1);
    atomicAdd(&out_ctx[b * ENC2 + e0 + 2], a2);
    atomicAdd(&out_ctx[b * ENC2 + e0 + 3], a3);
}

// ---------------------------------------------------------------------------
extern "C" void kernel_launch(void* const* d_in, const int* in_sizes, int n_in,
                              void* d_out, int out_size) {
    const float* dh    = (const float*)d_in[0];
    const float* enc   = (const float*)d_in[1];
    const int*   mask  = (const int*)d_in[2];
    const float* W_enc = (const float*)d_in[3];
    const float* b_enc = (const float*)d_in[4];
    const float* W_dec = (const float*)d_in[5];
    const float* b_dec = (const float*)d_in[6];
    const float* w_e   = (const float*)d_in[7];
    // d_in[8] = b_e : softmax-invariant, unused.

    float* out_ctx = (float*)d_out;
    float* out_w   = (float*)d_out + NB * ENC2;

    cudaFuncSetAttribute(k_energy, cudaFuncAttributeMaxDynamicSharedMemorySize,
                         SMEM_DYN);

    k_convert<<<2048, 256>>>(enc);
    k_transpose<<<dim3(32, 32), dim3(32, 8)>>>(W_enc);
    k_decproj<<<dim3(8, 4, 4), 128>>>(dh, W_dec, b_dec, b_enc);
    k_energy<<<dim3(8, 512), 512, SMEM_DYN>>>(w_e);
    k_softmax<<<32, 1024>>>(mask, out_w, out_ctx);
    k_context<<<dim3(32, 16), 256>>>(out_w, out_ctx);
}

// round 13
// speedup vs baseline: 1.0562x; 1.0562x over previous
#include <cuda_runtime.h>
#include <cuda_fp16.h>
#include <cstdint>

#define NB 32
#define NS 2048
#define ENC2 1024
#define DEC 1024
#define ATT 1024

#define BM 128
#define BN 128
#define BK 64                       // K halfs per chunk
#define ASTRH 72                    // smem row stride in halfs (144B): ldmatrix conflict-free
#define STG 3                       // cp.async pipeline stages
#define STAGE_H (BM * ASTRH)        // halfs per stage per array (9216)
#define STAGE_B (STAGE_H * 2)       // 18432 bytes
#define SMEM_DYN (STG * STAGE_B * 2)  // 110592 bytes

// scratch (no allocations allowed)
__device__ float  g_dp[NB * ATT];                       // decoder_proj + b_dec + b_enc
__device__ float  g_energy[NB * NS];                    // energies (b_e dropped)
__device__ __half g_ench[(size_t)NB * NS * ENC2];       // enc in fp16 (128 MB)
__device__ __half g_Wth[ATT * ENC2];                    // W_enc^T in fp16: Wt[n][k]

__device__ __forceinline__ uint32_t smem_u32(const void* p) {
    uint32_t a;
    asm("{ .reg .u64 t; cvta.to.shared.u64 t, %1; cvt.u32.u64 %0, t; }"
        : "=r"(a) : "l"(p));
    return a;
}
__device__ __forceinline__ uint2 f4_to_h4(float4 v) {
    half2 lo = __float22half2_rn(make_float2(v.x, v.y));
    half2 hi = __float22half2_rn(make_float2(v.z, v.w));
    uint2 u;
    u.x = *(uint32_t*)&lo;
    u.y = *(uint32_t*)&hi;
    return u;
}

// ---------------------------------------------------------------------------
// Kernel 0a: enc fp32 -> fp16; also zeroes g_dp and g_energy for this replay.
// 512 threads, 4-way unroll for MLP depth on the pure stream.
// ---------------------------------------------------------------------------
__global__ void k_convert(const float* __restrict__ enc) {
    const size_t total4 = (size_t)NB * NS * ENC2 / 4;   // 16M float4
    uint2* dst = (uint2*)g_ench;
    const float4* src = (const float4*)enc;
    const size_t gid = (size_t)blockIdx.x * blockDim.x + threadIdx.x;
    const size_t stride = (size_t)gridDim.x * blockDim.x;
    // total4 = 16M, stride = 1024*512 = 512K -> exactly 32 iterations, 4x unroll
    for (size_t p = gid; p < total4; p += 4 * stride) {
        float4 v0 = src[p];
        float4 v1 = src[p + stride];
        float4 v2 = src[p + 2 * stride];
        float4 v3 = src[p + 3 * stride];
        dst[p]              = f4_to_h4(v0);
        dst[p + stride]     = f4_to_h4(v1);
        dst[p + 2 * stride] = f4_to_h4(v2);
        dst[p + 3 * stride] = f4_to_h4(v3);
    }
    for (size_t i = gid; i < NB * ATT; i += stride) g_dp[i] = 0.f;
    for (size_t i = gid; i < NB * NS; i += stride) g_energy[i] = 0.f;
}

// ---------------------------------------------------------------------------
// Kernel 0b: transpose W_enc into g_Wth (n-major, k contiguous, fp16)
// ---------------------------------------------------------------------------
__global__ void k_transpose(const float* __restrict__ W) {
    __shared__ float t[32][33];
    const int x = blockIdx.x * 32 + threadIdx.x;   // n
    const int y0 = blockIdx.y * 32;                // k base
    for (int j = threadIdx.y; j < 32; j += 8)
        t[j][threadIdx.x] = W[(y0 + j) * ATT + x];
    __syncthreads();
    const int k = blockIdx.y * 32 + threadIdx.x;
    const int n0 = blockIdx.x * 32;
    for (int j = threadIdx.y; j < 32; j += 8)
        g_Wth[(size_t)(n0 + j) * ENC2 + k] = __float2half(t[threadIdx.x][j]);
}

// ---------------------------------------------------------------------------
// Kernel 1: dec_proj + bias fold, d-split x4 (atomicAdd into zeroed g_dp).
// grid (8 a-chunks, 4 b-chunks, 4 d-chunks), 128 threads.
// ---------------------------------------------------------------------------
__global__ void k_decproj(const float* __restrict__ dh,
                          const float* __restrict__ Wd,
                          const float* __restrict__ bd,
                          const float* __restrict__ ben) {
    __shared__ float sdh[8][256];
    const int a  = blockIdx.x * 128 + threadIdx.x;
    const int b0 = blockIdx.y * 8;
    const int d0 = blockIdx.z * 256;

    for (int i = threadIdx.x; i < 8 * 256; i += 128)
        sdh[i >> 8][i & 255] = dh[(b0 + (i >> 8)) * DEC + d0 + (i & 255)];
    __syncthreads();

    float acc[8];
#pragma unroll
    for (int bb = 0; bb < 8; bb++) acc[bb] = 0.f;
#pragma unroll 4
    for (int d = 0; d < 256; d++) {
        const float w = Wd[(d0 + d) * ATT + a];
#pragma unroll
        for (int bb = 0; bb < 8; bb++) acc[bb] += w * sdh[bb][d];
    }
    const float bias = (blockIdx.z == 0) ? (bd[a] + ben[a]) : 0.f;
#pragma unroll
    for (int bb = 0; bb < 8; bb++)
        atomicAdd(&g_dp[(b0 + bb) * ATT + a], acc[bb] + bias);
}

// ---------------------------------------------------------------------------
// Kernel 2: fused energy GEMM (R10 exact — measured 380.4us, tensor 59.7%).
// fp16 mma.sync + ldmatrix + 3-stage cp.async. CTA 128x128, K-chunk 64,
// 8 warps (4x2, warp tile 32x64), 2 CTAs/SM, tn fastest.
// ---------------------------------------------------------------------------
__global__ __launch_bounds__(256, 2)
void k_energy(const float* __restrict__ we_v) {
    extern __shared__ __align__(16) __half sh[];
    __half* As = sh;                     // [STG][STAGE_H]
    __half* Bs = sh + STG * STAGE_H;     // [STG][STAGE_H]

    const int tn = blockIdx.x;                  // 0..7   N tile (fastest)
    const int tm = blockIdx.y;                  // 0..511 M tile
    const int tid  = threadIdx.x;
    const int lane = tid & 31;
    const int warp = tid >> 5;
    const int wm = warp >> 1;                   // 0..3
    const int wn = warp & 1;                    // 0..1

    float acc[2][8][4];
#pragma unroll
    for (int i = 0; i < 2; i++)
#pragma unroll
        for (int j = 0; j < 8; j++)
#pragma unroll
            for (int k = 0; k < 4; k++) acc[i][j][k] = 0.f;

    size_t srcOff[4];
    uint32_t dstOff[4];
#pragma unroll
    for (int j = 0; j < 4; j++) {
        const int idx = tid + j * 256;
        const int row = idx >> 3, c16 = idx & 7;
        srcOff[j] = (size_t)row * ENC2 + c16 * 8;
        dstOff[j] = (uint32_t)(row * ASTRH + c16 * 8) * 2;
    }
    const __half* Ag = g_ench + (size_t)tm * BM * ENC2;
    const __half* Bg = g_Wth + (size_t)tn * BN * ENC2;
    const uint32_t asBase = smem_u32(As);
    const uint32_t bsBase = smem_u32(Bs);

    auto load_chunk = [&](int kc) {
        const int st = kc - (kc / STG) * STG;           // kc % 3
        const __half* a = Ag + kc * BK;
        const __half* b = Bg + kc * BK;
        const uint32_t sA = asBase + st * STAGE_B;
        const uint32_t sB = bsBase + st * STAGE_B;
#pragma unroll
        for (int j = 0; j < 4; j++) {
            asm volatile("cp.async.cg.shared.global [%0], [%1], 16;"
                         :: "r"(sA + dstOff[j]), "l"(a + srcOff[j]));
            asm volatile("cp.async.cg.shared.global [%0], [%1], 16;"
                         :: "r"(sB + dstOff[j]), "l"(b + srcOff[j]));
        }
        asm volatile("cp.async.commit_group;" ::: "memory");
    };

    const uint32_t aBase = asBase
        + (uint32_t)((wm * 32 + (lane & 15)) * (ASTRH * 2))
        + (uint32_t)(((lane >> 4) & 1) * 16);
    const uint32_t bBase = bsBase
        + (uint32_t)((wn * 64 + ((lane >> 4) & 1) * 8 + (lane & 7)) * (ASTRH * 2))
        + (uint32_t)(((lane >> 3) & 1) * 16);

    load_chunk(0);
    load_chunk(1);

    const int NKT = ENC2 / BK;  // 16
    for (int kt = 0; kt < NKT; kt++) {
        if (kt < NKT - 1)
            asm volatile("cp.async.wait_group 1;" ::: "memory");
        else
            asm volatile("cp.async.wait_group 0;" ::: "memory");
        __syncthreads();   // chunk kt visible; stage (kt+2)%3 readers (iter kt-1) done

        if (kt + 2 < NKT) load_chunk(kt + 2);

        const int st = kt - (kt / STG) * STG;
        const uint32_t stOff = (uint32_t)(st * STAGE_B);
        const uint32_t aAddr = aBase + stOff;
        const uint32_t bAddr = bBase + stOff;

#pragma unroll
        for (int ks = 0; ks < 4; ks++) {       // four k16 steps per 64-chunk
            uint32_t af[2][4];
#pragma unroll
            for (int mt = 0; mt < 2; mt++) {
                asm volatile(
                    "ldmatrix.sync.aligned.m8n8.x4.shared.b16 {%0,%1,%2,%3}, [%4];"
                    : "=r"(af[mt][0]), "=r"(af[mt][1]), "=r"(af[mt][2]), "=r"(af[mt][3])
                    : "r"(aAddr + (uint32_t)(mt * 16 * ASTRH * 2 + ks * 32)));
            }
            uint32_t bf[8][2];
#pragma unroll
            for (int p = 0; p < 4; p++) {
                asm volatile(
                    "ldmatrix.sync.aligned.m8n8.x4.shared.b16 {%0,%1,%2,%3}, [%4];"
                    : "=r"(bf[2 * p][0]), "=r"(bf[2 * p][1]),
                      "=r"(bf[2 * p + 1][0]), "=r"(bf[2 * p + 1][1])
                    : "r"(bAddr + (uint32_t)(p * 16 * ASTRH * 2 + ks * 32)));
            }
#pragma unroll
            for (int mt = 0; mt < 2; mt++)
#pragma unroll
                for (int nt = 0; nt < 8; nt++) {
                    float* d = acc[mt][nt];
                    asm volatile(
                        "mma.sync.aligned.m16n8k16.row.col.f32.f16.f16.f32 "
                        "{%0,%1,%2,%3}, {%4,%5,%6,%7}, {%8,%9}, {%0,%1,%2,%3};"
                        : "+f"(d[0]), "+f"(d[1]), "+f"(d[2]), "+f"(d[3])
                        : "r"(af[mt][0]), "r"(af[mt][1]), "r"(af[mt][2]), "r"(af[mt][3]),
                          "r"(bf[nt][0]), "r"(bf[nt][1]));
                }
        }
    }

    // ---- epilogue: tanh, weight by w_e, row-reduce, atomic into g_energy ----
    const int b = tm >> 4;   // 16 M-tiles per batch
    __syncthreads();
    float* dp_s = (float*)As;
    float* we_s = dp_s + BN;
    if (tid < BN) {
        dp_s[tid] = g_dp[b * ATT + tn * BN + tid];
        we_s[tid] = we_v[tn * BN + tid];
    }
    __syncthreads();

    const int r = lane >> 2, c = lane & 3;
    const float* dpp = dp_s + wn * 64;
    const float* wep = we_s + wn * 64;

#pragma unroll
    for (int mt = 0; mt < 2; mt++) {
#pragma unroll
        for (int rr = 0; rr < 2; rr++) {
            float rsum = 0.f;
#pragma unroll
            for (int nt = 0; nt < 8; nt++) {
#pragma unroll
                for (int cc = 0; cc < 2; cc++) {
                    const int col = nt * 8 + c * 2 + cc;
                    const float x = acc[mt][nt][rr * 2 + cc] + dpp[col];
                    rsum += tanhf(x) * wep[col];
                }
            }
            rsum += __shfl_xor_sync(0xffffffffu, rsum, 1);
            rsum += __shfl_xor_sync(0xffffffffu, rsum, 2);
            if (c == 0) {
                const int row = tm * BM + wm * 32 + mt * 16 + rr * 8 + r;
                atomicAdd(&g_energy[row], rsum);
            }
        }
    }
}

// ---------------------------------------------------------------------------
// Kernel 3a: masked softmax (mask = int32). Also zeroes out_ctx for 3b atomics.
// ---------------------------------------------------------------------------
__global__ void k_softmax(const int* __restrict__ mask,
                          float* __restrict__ out_w,
                          float* __restrict__ out_ctx) {
    const int b = blockIdx.x, t = threadIdx.x;
    __shared__ float red[32];
    const float NEG = __int_as_float(0xff800000);

    out_ctx[b * ENC2 + t] = 0.f;

    float e0 = g_energy[b * NS + t];
    float e1 = g_energy[b * NS + 1024 + t];
    bool m0 = mask[b * NS + t] != 0;
    bool m1 = mask[b * NS + 1024 + t] != 0;

    float v = fmaxf(m0 ? e0 : NEG, m1 ? e1 : NEG);
#pragma unroll
    for (int o = 16; o; o >>= 1) v = fmaxf(v, __shfl_xor_sync(0xffffffffu, v, o));
    if ((t & 31) == 0) red[t >> 5] = v;
    __syncthreads();
    if (t < 32) {
        float x = red[t];
#pragma unroll
        for (int o = 16; o; o >>= 1) x = fmaxf(x, __shfl_xor_sync(0xffffffffu, x, o));
        red[t] = x;
    }
    __syncthreads();
    const float mx = red[0];
    __syncthreads();

    float x0 = m0 ? __expf(e0 - mx) : 0.f;
    float x1 = m1 ? __expf(e1 - mx) : 0.f;
    float s = x0 + x1;
#pragma unroll
    for (int o = 16; o; o >>= 1) s += __shfl_xor_sync(0xffffffffu, s, o);
    if ((t & 31) == 0) red[t >> 5] = s;
    __syncthreads();
    if (t < 32) {
        float x = red[t];
#pragma unroll
        for (int o = 16; o; o >>= 1) x += __shfl_xor_sync(0xffffffffu, x, o);
        red[t] = x;
    }
    __syncthreads();
    const float inv = 1.0f / red[0];

    out_w[b * NS + t]        = x0 * inv;
    out_w[b * NS + 1024 + t] = x1 * inv;
}

// ---------------------------------------------------------------------------
// Kernel 3b: context from fp16 enc, full-row vectorized, split-S x32.
// grid (32 b, 32 s-chunks), 256 threads, each owns 4 consecutive e (uint2/8B).
// ---------------------------------------------------------------------------
__global__ void k_context(const float* __restrict__ w,
                          float* __restrict__ out_ctx) {
    const int b = blockIdx.x;
    const int s0 = blockIdx.y * 64;
    const int e0 = threadIdx.x * 4;

    const float* wp = w + b * NS;
    const __half* ep = g_ench + (size_t)b * NS * ENC2 + e0;

    float a0 = 0.f, a1 = 0.f, a2 = 0.f, a3 = 0.f;
#pragma unroll 1
    for (int s = s0; s < s0 + 64; s += 4) {
#pragma unroll
        for (int j = 0; j < 4; j++) {
            const float ws = wp[s + j];
            const uint2 u = *(const uint2*)(ep + (size_t)(s + j) * ENC2);
            const float2 f01 = __half22float2(*(const half2*)&u.x);
            const float2 f23 = __half22float2(*(const half2*)&u.y);
            a0 += ws * f01.x;
            a1 += ws * f01.y;
            a2 += ws * f23.x;
            a3 += ws * f23.y;
        }
    }
    atomicAdd(&out_ctx[b * ENC2 + e0],     a0);
    atomicAdd(&out_ctx[b * ENC2 + e0 + 1], a1);
    atomicAdd(&out_ctx[b * ENC2 + e0 + 2], a2);
    atomicAdd(&out_ctx[b * ENC2 + e0 + 3], a3);
}

// ---------------------------------------------------------------------------
extern "C" void kernel_launch(void* const* d_in, const int* in_sizes, int n_in,
                              void* d_out, int out_size) {
    const float* dh    = (const float*)d_in[0];
    const float* enc   = (const float*)d_in[1];
    const int*   mask  = (const int*)d_in[2];
    const float* W_enc = (const float*)d_in[3];
    const float* b_enc = (const float*)d_in[4];
    const float* W_dec = (const float*)d_in[5];
    const float* b_dec = (const float*)d_in[6];
    const float* w_e   = (const float*)d_in[7];
    // d_in[8] = b_e : softmax-invariant, unused.

    float* out_ctx = (float*)d_out;
    float* out_w   = (float*)d_out + NB * ENC2;

    cudaFuncSetAttribute(k_energy, cudaFuncAttributeMaxDynamicSharedMemorySize,
                         SMEM_DYN);

    k_convert<<<1024, 512>>>(enc);
    k_transpose<<<dim3(32, 32), dim3(32, 8)>>>(W_enc);
    k_decproj<<<dim3(8, 4, 4), 128>>>(dh, W_dec, b_dec, b_enc);
    k_energy<<<dim3(8, 512), 256, SMEM_DYN>>>(w_e);
    k_softmax<<<32, 1024>>>(mask, out_w, out_ctx);
    k_context<<<dim3(32, 32), 256>>>(out_w, out_ctx);
}

// round 14
// speedup vs baseline: 1.0855x; 1.0278x over previous
#include <cuda_runtime.h>
#include <cuda_fp16.h>
#include <cstdint>

#define NB 32
#define NS 2048
#define ENC2 1024
#define DEC 1024
#define ATT 1024

#define BM 128
#define BN 128
#define BK 64                       // K halfs per chunk
#define ASTRH 72                    // smem row stride in halfs (144B): ldmatrix conflict-free
#define STG 3                       // cp.async pipeline stages
#define STAGE_H (BM * ASTRH)        // halfs per stage per array (9216)
#define STAGE_B (STAGE_H * 2)       // 18432 bytes
#define SMEM_DYN (STG * STAGE_B * 2)  // 110592 bytes

// prep-kernel block-role split
#define NCONV 2048
#define NTRANS 1024
#define NDEC 64

// scratch (no allocations allowed)
__device__ float  g_dp4[4][NB * ATT];                   // decoder_proj partials (d-split)
__device__ float  g_energy[NB * NS];                    // energies (b_e dropped)
__device__ __half g_ench[(size_t)NB * NS * ENC2];       // enc in fp16 (128 MB)
__device__ __half g_Wth[ATT * ENC2];                    // W_enc^T in fp16: Wt[n][k]

__device__ __forceinline__ uint32_t smem_u32(const void* p) {
    uint32_t a;
    asm("{ .reg .u64 t; cvta.to.shared.u64 t, %1; cvt.u32.u64 %0, t; }"
        : "=r"(a) : "l"(p));
    return a;
}
__device__ __forceinline__ uint2 f4_to_h4(float4 v) {
    half2 lo = __float22half2_rn(make_float2(v.x, v.y));
    half2 hi = __float22half2_rn(make_float2(v.z, v.w));
    uint2 u;
    u.x = *(uint32_t*)&lo;
    u.y = *(uint32_t*)&hi;
    return u;
}

// ---------------------------------------------------------------------------
// Kernel 0: fused prep. Block roles:
//   [0, NCONV)                : enc fp32->fp16 (uint4 stores) + zero g_energy
//   [NCONV, NCONV+NTRANS)     : W_enc transpose -> g_Wth (fp16, n-major)
//   [NCONV+NTRANS, +NDEC)     : dec_proj d-split partials -> g_dp4 (plain stores)
// All roles independent; 256 threads each.
// ---------------------------------------------------------------------------
__global__ __launch_bounds__(256)
void k_prep(const float* __restrict__ enc,
            const float* __restrict__ W,
            const float* __restrict__ dh,
            const float* __restrict__ Wd,
            const float* __restrict__ bd,
            const float* __restrict__ ben) {
    __shared__ float sbuf[8 * 256];      // decproj: sdh[8][256]; transpose: 32x33 tile
    const int blk = blockIdx.x;
    const int tid = threadIdx.x;

    if (blk < NCONV) {
        // ---- convert role: 8M uint4 outputs over 512K threads -> 16 iters ----
        const size_t total_u4 = (size_t)NB * NS * ENC2 / 8;     // 8M
        uint4* dst = (uint4*)g_ench;
        const float4* src = (const float4*)enc;
        const size_t gid = (size_t)blk * 256 + tid;
        const size_t stride = (size_t)NCONV * 256;              // 512K
        for (size_t p = gid; p < total_u4; p += 2 * stride) {
            const float4 a0 = src[2 * p];
            const float4 a1 = src[2 * p + 1];
            const size_t q = p + stride;
            const float4 b0 = src[2 * q];
            const float4 b1 = src[2 * q + 1];
            uint2 ua0 = f4_to_h4(a0), ua1 = f4_to_h4(a1);
            uint2 ub0 = f4_to_h4(b0), ub1 = f4_to_h4(b1);
            uint4 ua = {ua0.x, ua0.y, ua1.x, ua1.y};
            uint4 ub = {ub0.x, ub0.y, ub1.x, ub1.y};
            dst[p] = ua;
            dst[q] = ub;
        }
        for (size_t i = gid; i < NB * NS; i += stride) g_energy[i] = 0.f;
    } else if (blk < NCONV + NTRANS) {
        // ---- transpose role ----
        float (*t)[33] = (float (*)[33])sbuf;    // 32x33 within 8KB
        const int tb = blk - NCONV;
        const int bx = tb & 31;                  // n tile
        const int by = tb >> 5;                  // k tile
        const int tx = tid & 31;
        const int ty = tid >> 5;                 // 0..7
        const int x = bx * 32 + tx;              // n
        const int y0 = by * 32;                  // k base
        for (int j = ty; j < 32; j += 8)
            t[j][tx] = W[(y0 + j) * ATT + x];
        __syncthreads();
        const int k = by * 32 + tx;
        const int n0 = bx * 32;
        for (int j = ty; j < 32; j += 8)
            g_Wth[(size_t)(n0 + j) * ENC2 + k] = __float2half(t[tx][j]);
    } else {
        // ---- decproj role: 64 blocks = (4 a) x (4 b) x (4 d) ----
        float (*sdh)[256] = (float (*)[256])sbuf;
        const int db = blk - NCONV - NTRANS;
        const int a  = (db & 3) * 256 + tid;
        const int b0 = ((db >> 2) & 3) * 8;
        const int dc = db >> 4;                  // d-chunk 0..3
        const int d0 = dc * 256;

        for (int i = tid; i < 8 * 256; i += 256)
            sdh[i >> 8][i & 255] = dh[(b0 + (i >> 8)) * DEC + d0 + (i & 255)];
        __syncthreads();

        float acc[8];
#pragma unroll
        for (int bb = 0; bb < 8; bb++) acc[bb] = 0.f;
#pragma unroll 4
        for (int d = 0; d < 256; d++) {
            const float w = Wd[(d0 + d) * ATT + a];
#pragma unroll
            for (int bb = 0; bb < 8; bb++) acc[bb] += w * sdh[bb][d];
        }
        const float bias = (dc == 0) ? (bd[a] + ben[a]) : 0.f;
#pragma unroll
        for (int bb = 0; bb < 8; bb++)
            g_dp4[dc][(b0 + bb) * ATT + a] = acc[bb] + bias;
    }
}

// ---------------------------------------------------------------------------
// Kernel 2: fused energy GEMM (R10 structure — 379-381us, tensor ~60%).
// fp16 mma.sync + ldmatrix + 3-stage cp.async. CTA 128x128, K-chunk 64,
// 8 warps (4x2, warp tile 32x64), 2 CTAs/SM, tn fastest.
// ---------------------------------------------------------------------------
__global__ __launch_bounds__(256, 2)
void k_energy(const float* __restrict__ we_v) {
    extern __shared__ __align__(16) __half sh[];
    __half* As = sh;                     // [STG][STAGE_H]
    __half* Bs = sh + STG * STAGE_H;     // [STG][STAGE_H]

    const int tn = blockIdx.x;                  // 0..7   N tile (fastest)
    const int tm = blockIdx.y;                  // 0..511 M tile
    const int tid  = threadIdx.x;
    const int lane = tid & 31;
    const int warp = tid >> 5;
    const int wm = warp >> 1;                   // 0..3
    const int wn = warp & 1;                    // 0..1

    float acc[2][8][4];
#pragma unroll
    for (int i = 0; i < 2; i++)
#pragma unroll
        for (int j = 0; j < 8; j++)
#pragma unroll
            for (int k = 0; k < 4; k++) acc[i][j][k] = 0.f;

    size_t srcOff[4];
    uint32_t dstOff[4];
#pragma unroll
    for (int j = 0; j < 4; j++) {
        const int idx = tid + j * 256;
        const int row = idx >> 3, c16 = idx & 7;
        srcOff[j] = (size_t)row * ENC2 + c16 * 8;
        dstOff[j] = (uint32_t)(row * ASTRH + c16 * 8) * 2;
    }
    const __half* Ag = g_ench + (size_t)tm * BM * ENC2;
    const __half* Bg = g_Wth + (size_t)tn * BN * ENC2;
    const uint32_t asBase = smem_u32(As);
    const uint32_t bsBase = smem_u32(Bs);

    auto load_chunk = [&](int kc) {
        const int st = kc - (kc / STG) * STG;           // kc % 3
        const __half* a = Ag + kc * BK;
        const __half* b = Bg + kc * BK;
        const uint32_t sA = asBase + st * STAGE_B;
        const uint32_t sB = bsBase + st * STAGE_B;
#pragma unroll
        for (int j = 0; j < 4; j++) {
            asm volatile("cp.async.cg.shared.global [%0], [%1], 16;"
                         :: "r"(sA + dstOff[j]), "l"(a + srcOff[j]));
            asm volatile("cp.async.cg.shared.global [%0], [%1], 16;"
                         :: "r"(sB + dstOff[j]), "l"(b + srcOff[j]));
        }
        asm volatile("cp.async.commit_group;" ::: "memory");
    };

    const uint32_t aBase = asBase
        + (uint32_t)((wm * 32 + (lane & 15)) * (ASTRH * 2))
        + (uint32_t)(((lane >> 4) & 1) * 16);
    const uint32_t bBase = bsBase
        + (uint32_t)((wn * 64 + ((lane >> 4) & 1) * 8 + (lane & 7)) * (ASTRH * 2))
        + (uint32_t)(((lane >> 3) & 1) * 16);

    load_chunk(0);
    load_chunk(1);

    const int NKT = ENC2 / BK;  // 16
    for (int kt = 0; kt < NKT; kt++) {
        if (kt < NKT - 1)
            asm volatile("cp.async.wait_group 1;" ::: "memory");
        else
            asm volatile("cp.async.wait_group 0;" ::: "memory");
        __syncthreads();   // chunk kt visible; stage (kt+2)%3 readers (iter kt-1) done

        if (kt + 2 < NKT) load_chunk(kt + 2);

        const int st = kt - (kt / STG) * STG;
        const uint32_t stOff = (uint32_t)(st * STAGE_B);
        const uint32_t aAddr = aBase + stOff;
        const uint32_t bAddr = bBase + stOff;

#pragma unroll
        for (int ks = 0; ks < 4; ks++) {       // four k16 steps per 64-chunk
            uint32_t af[2][4];
#pragma unroll
            for (int mt = 0; mt < 2; mt++) {
                asm volatile(
                    "ldmatrix.sync.aligned.m8n8.x4.shared.b16 {%0,%1,%2,%3}, [%4];"
                    : "=r"(af[mt][0]), "=r"(af[mt][1]), "=r"(af[mt][2]), "=r"(af[mt][3])
                    : "r"(aAddr + (uint32_t)(mt * 16 * ASTRH * 2 + ks * 32)));
            }
            uint32_t bf[8][2];
#pragma unroll
            for (int p = 0; p < 4; p++) {
                asm volatile(
                    "ldmatrix.sync.aligned.m8n8.x4.shared.b16 {%0,%1,%2,%3}, [%4];"
                    : "=r"(bf[2 * p][0]), "=r"(bf[2 * p][1]),
                      "=r"(bf[2 * p + 1][0]), "=r"(bf[2 * p + 1][1])
                    : "r"(bAddr + (uint32_t)(p * 16 * ASTRH * 2 + ks * 32)));
            }
#pragma unroll
            for (int mt = 0; mt < 2; mt++)
#pragma unroll
                for (int nt = 0; nt < 8; nt++) {
                    float* d = acc[mt][nt];
                    asm volatile(
                        "mma.sync.aligned.m16n8k16.row.col.f32.f16.f16.f32 "
                        "{%0,%1,%2,%3}, {%4,%5,%6,%7}, {%8,%9}, {%0,%1,%2,%3};"
                        : "+f"(d[0]), "+f"(d[1]), "+f"(d[2]), "+f"(d[3])
                        : "r"(af[mt][0]), "r"(af[mt][1]), "r"(af[mt][2]), "r"(af[mt][3]),
                          "r"(bf[nt][0]), "r"(bf[nt][1]));
                }
        }
    }

    // ---- epilogue: sum dp partials, tanh, weight, row-reduce, atomicAdd ----
    const int b = tm >> 4;   // 16 M-tiles per batch
    __syncthreads();
    float* dp_s = (float*)As;
    float* we_s = dp_s + BN;
    if (tid < BN) {
        const int gi = b * ATT + tn * BN + tid;
        dp_s[tid] = g_dp4[0][gi] + g_dp4[1][gi] + g_dp4[2][gi] + g_dp4[3][gi];
        we_s[tid] = we_v[tn * BN + tid];
    }
    __syncthreads();

    const int r = lane >> 2, c = lane & 3;
    const float* dpp = dp_s + wn * 64;
    const float* wep = we_s + wn * 64;

#pragma unroll
    for (int mt = 0; mt < 2; mt++) {
#pragma unroll
        for (int rr = 0; rr < 2; rr++) {
            float rsum = 0.f;
#pragma unroll
            for (int nt = 0; nt < 8; nt++) {
#pragma unroll
                for (int cc = 0; cc < 2; cc++) {
                    const int col = nt * 8 + c * 2 + cc;
                    const float x = acc[mt][nt][rr * 2 + cc] + dpp[col];
                    rsum += tanhf(x) * wep[col];
                }
            }
            rsum += __shfl_xor_sync(0xffffffffu, rsum, 1);
            rsum += __shfl_xor_sync(0xffffffffu, rsum, 2);
            if (c == 0) {
                const int row = tm * BM + wm * 32 + mt * 16 + rr * 8 + r;
                atomicAdd(&g_energy[row], rsum);
            }
        }
    }
}

// ---------------------------------------------------------------------------
// Kernel 3a: masked softmax (mask = int32). Also zeroes out_ctx for 3b atomics.
// ---------------------------------------------------------------------------
__global__ void k_softmax(const int* __restrict__ mask,
                          float* __restrict__ out_w,
                          float* __restrict__ out_ctx) {
    const int b = blockIdx.x, t = threadIdx.x;
    __shared__ float red[32];
    const float NEG = __int_as_float(0xff800000);

    out_ctx[b * ENC2 + t] = 0.f;

    float e0 = g_energy[b * NS + t];
    float e1 = g_energy[b * NS + 1024 + t];
    bool m0 = mask[b * NS + t] != 0;
    bool m1 = mask[b * NS + 1024 + t] != 0;

    float v = fmaxf(m0 ? e0 : NEG, m1 ? e1 : NEG);
#pragma unroll
    for (int o = 16; o; o >>= 1) v = fmaxf(v, __shfl_xor_sync(0xffffffffu, v, o));
    if ((t & 31) == 0) red[t >> 5] = v;
    __syncthreads();
    if (t < 32) {
        float x = red[t];
#pragma unroll
        for (int o = 16; o; o >>= 1) x = fmaxf(x, __shfl_xor_sync(0xffffffffu, x, o));
        red[t] = x;
    }
    __syncthreads();
    const float mx = red[0];
    __syncthreads();

    float x0 = m0 ? __expf(e0 - mx) : 0.f;
    float x1 = m1 ? __expf(e1 - mx) : 0.f;
    float s = x0 + x1;
#pragma unroll
    for (int o = 16; o; o >>= 1) s += __shfl_xor_sync(0xffffffffu, s, o);
    if ((t & 31) == 0) red[t >> 5] = s;
    __syncthreads();
    if (t < 32) {
        float x = red[t];
#pragma unroll
        for (int o = 16; o; o >>= 1) x += __shfl_xor_sync(0xffffffffu, x, o);
        red[t] = x;
    }
    __syncthreads();
    const float inv = 1.0f / red[0];

    out_w[b * NS + t]        = x0 * inv;
    out_w[b * NS + 1024 + t] = x1 * inv;
}

// ---------------------------------------------------------------------------
// Kernel 3b: context from fp16 enc, full-row vectorized, split-S x32.
// grid (32 b, 32 s-chunks), 256 threads, each owns 4 consecutive e (uint2/8B).
// ---------------------------------------------------------------------------
__global__ void k_context(const float* __restrict__ w,
                          float* __restrict__ out_ctx) {
    const int b = blockIdx.x;
    const int s0 = blockIdx.y * 64;
    const int e0 = threadIdx.x * 4;

    const float* wp = w + b * NS;
    const __half* ep = g_ench + (size_t)b * NS * ENC2 + e0;

    float a0 = 0.f, a1 = 0.f, a2 = 0.f, a3 = 0.f;
#pragma unroll 1
    for (int s = s0; s < s0 + 64; s += 4) {
#pragma unroll
        for (int j = 0; j < 4; j++) {
            const float ws = wp[s + j];
            const uint2 u = *(const uint2*)(ep + (size_t)(s + j) * ENC2);
            const float2 f01 = __half22float2(*(const half2*)&u.x);
            const float2 f23 = __half22float2(*(const half2*)&u.y);
            a0 += ws * f01.x;
            a1 += ws * f01.y;
            a2 += ws * f23.x;
            a3 += ws * f23.y;
        }
    }
    atomicAdd(&out_ctx[b * ENC2 + e0],     a0);
    atomicAdd(&out_ctx[b * ENC2 + e0 + 1], a1);
    atomicAdd(&out_ctx[b * ENC2 + e0 + 2], a2);
    atomicAdd(&out_ctx[b * ENC2 + e0 + 3], a3);
}

// ---------------------------------------------------------------------------
extern "C" void kernel_launch(void* const* d_in, const int* in_sizes, int n_in,
                              void* d_out, int out_size) {
    const float* dh    = (const float*)d_in[0];
    const float* enc   = (const float*)d_in[1];
    const int*   mask  = (const int*)d_in[2];
    const float* W_enc = (const float*)d_in[3];
    const float* b_enc = (const float*)d_in[4];
    const float* W_dec = (const float*)d_in[5];
    const float* b_dec = (const float*)d_in[6];
    const float* w_e   = (const float*)d_in[7];
    // d_in[8] = b_e : softmax-invariant, unused.

    float* out_ctx = (float*)d_out;
    float* out_w   = (float*)d_out + NB * ENC2;

    cudaFuncSetAttribute(k_energy, cudaFuncAttributeMaxDynamicSharedMemorySize,
                         SMEM_DYN);

    k_prep<<<NCONV + NTRANS + NDEC, 256>>>(enc, W_enc, dh, W_dec, b_dec, b_enc);
    k_energy<<<dim3(8, 512), 256, SMEM_DYN>>>(w_e);
    k_softmax<<<32, 1024>>>(mask, out_w, out_ctx);
    k_context<<<dim3(32, 32), 256>>>(out_w, out_ctx);
}